// round 5
// baseline (speedup 1.0000x reference)
#include <cuda_runtime.h>
#include <math.h>

// ---------------- problem constants ----------------
#define NCC 10
#define DM  512
#define HH  8
#define DKk 64
#define BBa 8
#define LLn 2048
#define LK  228
#define UF  100
#define NROWS (BBa*LK*UF)          // 182400
#define KPSZ  (512*LK)             // 116736 per batch
#define GSZ   (NCC*BBa*LK*DM)      // 9338880
#define CCSZ  (BBa*HH*LK*DKk)      // 933888
#define CTXN  (BBa*HH*LLn*DKk)     // 8388608
#define MLP_THREADS 384
#define MLP_BLOCKS (NROWS/MLP_THREADS)   // 475 exact

// ---------------- device scratch ----------------
__device__ float g_Kp[BBa*KPSZ];
__device__ float g_Vp[BBa*KPSZ];
__device__ float g_cq[NROWS*NCC];
__device__ float g_mu[NROWS];
__device__ float g_G[GSZ];
__device__ float g_CC[CCSZ];
__device__ float g_lp[MLP_BLOCKS];
__device__ float g_ce[800];

// ---------------- helpers ----------------
__device__ __forceinline__ float gelu_exact(float x) {
    return 0.5f * x * (1.0f + erff(x * 0.70710678118654752f));
}

typedef unsigned long long ull;
__device__ __forceinline__ void fma2(ull& d, ull a, ull b) {
    asm("fma.rn.f32x2 %0, %1, %2, %0;" : "+l"(d) : "l"(a), "l"(b));
}
__device__ __forceinline__ void mul2(ull& d, ull a, ull b) {
    asm("mul.rn.f32x2 %0, %1, %2;" : "=l"(d) : "l"(a), "l"(b));
}
__device__ __forceinline__ ull pack2(float lo, float hi) {
    ull v;
    asm("mov.b64 %0, {%1, %2};" : "=l"(v) : "r"(__float_as_uint(lo)), "r"(__float_as_uint(hi)));
    return v;
}
__device__ __forceinline__ ull dup2(float x) { return pack2(x, x); }
__device__ __forceinline__ void unpack2(ull v, float& lo, float& hi) {
    unsigned int a, b;
    asm("mov.b64 {%0, %1}, %2;" : "=r"(a), "=r"(b) : "l"(v));
    lo = __uint_as_float(a); hi = __uint_as_float(b);
}
__device__ __forceinline__ float hsum2(ull v) {
    float lo, hi; unpack2(v, lo, hi); return lo + hi;
}

// ---------------- 1. max pool ----------------
__global__ void pool_kernel(const float* __restrict__ K, const float* __restrict__ V) {
    int idx = blockIdx.x * 256 + threadIdx.x;           // < 933888
    int b = idx / KPSZ;
    int rem = idx - b * KPSZ;
    int c = rem / LK;
    int t2 = rem - c * LK;
    int t0 = t2 * 9 - 4;
    int lo = t0 < 0 ? 0 : t0;
    int hi = t0 + 9 > 2048 ? 2048 : t0 + 9;
    const float* kp = K + ((size_t)b * 512 + c) * 2048;
    const float* vp = V + ((size_t)b * 512 + c) * 2048;
    float mk = -INFINITY, mv = -INFINITY;
    for (int t = lo; t < hi; ++t) { mk = fmaxf(mk, kp[t]); mv = fmaxf(mv, vp[t]); }
    g_Kp[idx] = mk;
    g_Vp[idx] = mv;
}

// ---------------- 2. sparse-gather double MLP (packed f32x2) ----------------
__global__ __launch_bounds__(MLP_THREADS) void mlp_kernel(
    const float* __restrict__ Wk1, const float* __restrict__ bk1,
    const float* __restrict__ Wk2, const float* __restrict__ bk2,
    const float* __restrict__ Wq1, const float* __restrict__ bq1,
    const float* __restrict__ Wq2, const float* __restrict__ bq2)
{
    extern __shared__ float sw[];
    float* sWk1 = sw;               // 512*40
    float* sWq1 = sw + 20480;       // 512*40
    __shared__ __align__(16) float sWk2[400], sWq2[400];
    __shared__ __align__(16) float sbk1[40], sbq1[40], sbk2[16], sbq2[16];
    __shared__ float warpsum[12];
    for (int i = threadIdx.x; i < 20480; i += MLP_THREADS) { sWk1[i] = Wk1[i]; sWq1[i] = Wq1[i]; }
    for (int i = threadIdx.x; i < 400; i += MLP_THREADS) { sWk2[i] = Wk2[i]; sWq2[i] = Wq2[i]; }
    if (threadIdx.x < 40) { sbk1[threadIdx.x] = bk1[threadIdx.x]; sbq1[threadIdx.x] = bq1[threadIdx.x]; }
    if (threadIdx.x < 10) { sbk2[threadIdx.x] = bk2[threadIdx.x]; sbq2[threadIdx.x] = bq2[threadIdx.x]; }
    __syncthreads();

    int r = blockIdx.x * MLP_THREADS + threadIdx.x;   // always < NROWS (exact grid)
    float lp;
    {
        int b  = r / (LK * UF);
        int l2 = (r / UF) % LK;
        int u2 = r % UF;

        ull ak2[20], aq2[20];
        {
            const ull* pk = (const ull*)sbk1;
            const ull* pq = (const ull*)sbq1;
            #pragma unroll
            for (int j = 0; j < 20; ++j) { ak2[j] = pk[j]; aq2[j] = pq[j]; }
        }

        int m12 = (12 * u2) % 100;
        int base = u2 * 512;
        for (int u = 100 - b; u < 100; ++u) {      // empty when b == 0
            int bp_ = u + b - 99;                  // source batch 1..b
            int c0 = u - m12; if (c0 < 0) c0 += 100;
            const float* kpr = g_Kp + bp_ * KPSZ + l2 * 512;
            for (int c2 = c0; c2 < 512; c2 += 100) {
                int q = (base + c2 - u) / 100;     // exact division
                ull v2 = dup2(__ldg(kpr + q));
                const ull* w1 = (const ull*)(sWk1 + c2 * 40);
                const ull* w2 = (const ull*)(sWq1 + c2 * 40);
                #pragma unroll
                for (int jj = 0; jj < 20; ++jj) {
                    fma2(ak2[jj], v2, w1[jj]);
                    fma2(aq2[jj], v2, w2[jj]);
                }
            }
        }
        float hk[40], hq[40];
        #pragma unroll
        for (int j = 0; j < 20; ++j) {
            unpack2(ak2[j], hk[2*j], hk[2*j+1]);
            unpack2(aq2[j], hq[2*j], hq[2*j+1]);
        }
        #pragma unroll
        for (int j = 0; j < 40; ++j) { hk[j] = gelu_exact(hk[j]); hq[j] = gelu_exact(hq[j]); }

        ull ok2[5], oq2[5];
        {
            const ull* pk = (const ull*)sbk2;
            const ull* pq = (const ull*)sbq2;
            #pragma unroll
            for (int p = 0; p < 5; ++p) { ok2[p] = pk[p]; oq2[p] = pq[p]; }
        }
        #pragma unroll
        for (int j = 0; j < 40; ++j) {
            ull hk2 = dup2(hk[j]);
            ull hq2 = dup2(hq[j]);
            const ull* w2k = (const ull*)(sWk2 + j * 10);
            const ull* w2q = (const ull*)(sWq2 + j * 10);
            #pragma unroll
            for (int p = 0; p < 5; ++p) {
                fma2(ok2[p], hk2, w2k[p]);
                fma2(oq2[p], hq2, w2q[p]);
            }
        }
        float ok[10], oq[10];
        #pragma unroll
        for (int p = 0; p < 5; ++p) {
            unpack2(ok2[p], ok[2*p], ok[2*p+1]);
            unpack2(oq2[p], oq[2*p], oq[2*p+1]);
        }
        float mk = ok[0], mq = oq[0];
        #pragma unroll
        for (int i = 1; i < 10; ++i) { mk = fmaxf(mk, ok[i]); mq = fmaxf(mq, oq[i]); }
        float sk = 0.0f, sq = 0.0f;
        float ckv[10], cqv[10];
        #pragma unroll
        for (int i = 0; i < 10; ++i) {
            ckv[i] = __expf(ok[i] - mk); sk += ckv[i];
            cqv[i] = __expf(oq[i] - mq); sq += cqv[i];
        }
        float isk = 1.0f / sk, isq = 1.0f / sq;
        float* dst = g_cq + (size_t)r * NCC;
        float sumq = 0.0f, sumk = 0.0f;
        #pragma unroll
        for (int i = 0; i < 10; ++i) {
            ckv[i] *= isk; cqv[i] *= isq;
            dst[i] = cqv[i];
            sumq += cqv[i]; sumk += ckv[i];
        }
        float mu = sumq * 0.1f;
        float x  = sumk * 0.1f;
        float ssd = 0.0f;
        #pragma unroll
        for (int i = 0; i < 10; ++i) { float d = cqv[i] - mu; ssd = fmaf(d, d, ssd); }
        float stdv = sqrtf(ssd * (1.0f / 9.0f));
        float sigma = log1pf(__expf(stdv));      // softplus
        float z = (x - mu) / sigma;
        lp = -0.5f * z * z - logf(sigma) - 0.9189385332046727f;
        g_mu[r] = mu;
    }
    // deterministic reduction
    #pragma unroll
    for (int o = 16; o; o >>= 1) lp += __shfl_xor_sync(0xFFFFFFFFu, lp, o);
    int wid = threadIdx.x >> 5;
    if ((threadIdx.x & 31) == 0) warpsum[wid] = lp;
    __syncthreads();
    if (threadIdx.x == 0) {
        float s = 0.0f;
        #pragma unroll
        for (int i = 0; i < 12; ++i) s += warpsum[i];
        g_lp[blockIdx.x] = s;
    }
}

// ---------------- 3. CE (branchless online LSE, coalesced lanes) ----------------
__global__ void ce_kernel() {
    int b = blockIdx.x;
    int u = threadIdx.x;
    if (u >= UF) return;
    const float* p = g_mu + (size_t)b * LK * UF + u;
    float m = -INFINITY, se = 0.0f, s1 = 0.0f, s2 = 0.0f;
    #pragma unroll 4
    for (int l = 0; l < LK; ++l) {
        float v = p[l * UF];
        float mn = fmaxf(m, v);
        se = fmaf(se, __expf(m - mn), __expf(v - mn));
        m = mn;
        s1 += v;
        s2 = fmaf(v, v, s2);
    }
    float lse = m + logf(se);
    g_ce[b * UF + u] = lse * s1 - s2;   // = -sum_l mu*(mu - lse)
}

// ---------------- 4. centers + proj_back (packed f32x2) ----------------
__global__ __launch_bounds__(256) void centers_kernel(const float* __restrict__ Wp, const float* __restrict__ bp) {
    int bl = blockIdx.x;            // 0..1823  (= bb*228 + l)
    int bb = bl / LK, l = bl % LK;
    __shared__ __align__(16) float scq[UF * NCC];   // 1000
    __shared__ int   sassign[UF];
    __shared__ float scen[NCC * NCC]; // 100
    __shared__ __align__(16) float sWp[NCC * DM];   // 5120
    __shared__ __align__(16) float sbp[DM];
    {
        const float4* src = (const float4*)(g_cq + (size_t)bl * UF * NCC);
        for (int i = threadIdx.x; i < UF * NCC / 4; i += 256) ((float4*)scq)[i] = src[i];
        const float4* wsrc = (const float4*)Wp;
        for (int i = threadIdx.x; i < NCC * DM / 4; i += 256) ((float4*)sWp)[i] = wsrc[i];
        const float4* bsrc = (const float4*)bp;
        for (int i = threadIdx.x; i < DM / 4; i += 256) ((float4*)sbp)[i] = bsrc[i];
    }
    __syncthreads();
    if (threadIdx.x < UF) {
        const float* row = scq + threadIdx.x * NCC;
        int am = 0; float mv = row[0];
        #pragma unroll
        for (int c = 1; c < NCC; ++c) if (row[c] > mv) { mv = row[c]; am = c; }
        sassign[threadIdx.x] = am;
    }
    __syncthreads();
    if (threadIdx.x < 100) {
        int i = threadIdx.x / 10, c = threadIdx.x % 10;
        float s = 0.0f;
        for (int u = 0; u < UF; ++u)
            if (sassign[u] != i) s += scq[u * NCC + c];
        scen[i * 10 + c] = s * 0.01f;
    }
    __syncthreads();
    // projection: 1280 float4 outputs, 5 per thread, packed fma
    for (int i4 = threadIdx.x; i4 < NCC * (DM/4); i4 += 256) {
        int i = i4 >> 7;            // cluster index 0..9
        int m4 = i4 & 127;          // float4 index within 512
        ull d0 = ((const ull*)sbp)[2*m4];
        ull d1 = ((const ull*)sbp)[2*m4+1];
        const float* ce = scen + i * 10;
        #pragma unroll
        for (int c = 0; c < NCC; ++c) {
            const ull* wv = (const ull*)(sWp + c * DM + 4*m4);
            ull cv = dup2(ce[c]);
            fma2(d0, cv, wv[0]);
            fma2(d1, cv, wv[1]);
        }
        float4 a;
        unpack2(d0, a.x, a.y);
        unpack2(d1, a.z, a.w);
        a.x = gelu_exact(a.x); a.y = gelu_exact(a.y);
        a.z = gelu_exact(a.z); a.w = gelu_exact(a.w);
        ((float4*)(g_G + (size_t)i * (BBa * LK * DM) + bb * (LK * DM) + l * DM))[m4] = a;
    }
}

// ---------------- 5. CC: reshape-sum over the 10 'c' slices (float4) ----------------
__global__ void cc_kernel() {
    int o4 = blockIdx.x * 256 + threadIdx.x;       // < 233472
    if (o4 >= CCSZ / 4) return;
    int o = o4 * 4;
    int b2 = o / (HH * LK * DKk);
    int h2 = (o / (LK * DKk)) % HH;
    int rest = o % (LK * DKk);
    int basei4 = (b2 * 1167360 + h2 * 145920 + rest) >> 2;
    const float4* G4 = (const float4*)g_G;
    float4 s = G4[basei4];
    #pragma unroll
    for (int i2 = 1; i2 < NCC; ++i2) {
        float4 t = G4[basei4 + i2 * 3648];
        s.x += t.x; s.y += t.y; s.z += t.z; s.w += t.w;
    }
    ((float4*)g_CC)[o4] = s;
}

// ---------------- 6. attention: 2-lane cooperative q-rows, online softmax ----------------
// 512 threads/block; lane pair (2t, 2t+1) handles q-row t; each lane owns 32 of 64 dims.
__global__ __launch_bounds__(512, 1) void attn_kernel(const float* __restrict__ Q, float* __restrict__ out) {
    extern __shared__ float sm[];
    float* sCC = sm;                  // 228*64
    float* sV  = sm + LK * DKk;       // 228*64
    int bh = blockIdx.x >> 3;         // 0..63
    int qt = blockIdx.x & 7;
    int b = bh >> 3, h = bh & 7;
    {
        const float4* srcC = (const float4*)(g_CC + (size_t)bh * (LK * DKk));
        const float4* srcV = (const float4*)(g_Vp + (size_t)b * KPSZ + h * (LK * DKk));
        float4* dC = (float4*)sCC;
        float4* dV = (float4*)sV;
        for (int i = threadIdx.x; i < LK * DKk / 4; i += 512) { dC[i] = srcC[i]; dV[i] = srcV[i]; }
    }
    __syncthreads();

    int row  = threadIdx.x >> 1;           // 0..255
    int half = threadIdx.x & 1;            // which 32-dim half
    int qi = qt * 256 + row;
    int hoff = half * 32;                  // float offset of this lane's half

    ull qv[16];
    {
        const float4* qr = (const float4*)(Q + ((size_t)bh * LLn + qi) * DKk + hoff);
        #pragma unroll
        for (int j = 0; j < 8; ++j) {
            float4 t = qr[j];
            qv[2*j]   = pack2(t.x * 0.125f, t.y * 0.125f);
            qv[2*j+1] = pack2(t.z * 0.125f, t.w * 0.125f);
        }
    }

    float m = -INFINITY, lsum = 0.0f;
    ull acc[16];
    #pragma unroll
    for (int i = 0; i < 16; ++i) acc[i] = 0ull;

    const float* ccp = sCC + hoff;
    const float* vvp = sV  + hoff;
    for (int k = 0; k < LK; ++k) {
        const ull* cc = (const ull*)(ccp + (k << 6));
        ull d0 = 0ull, d1 = 0ull, d2 = 0ull, d3 = 0ull;
        #pragma unroll
        for (int j = 0; j < 16; j += 4) {
            fma2(d0, qv[j],     cc[j]);
            fma2(d1, qv[j + 1], cc[j + 1]);
            fma2(d2, qv[j + 2], cc[j + 2]);
            fma2(d3, qv[j + 3], cc[j + 3]);
        }
        float partial = (hsum2(d0) + hsum2(d1)) + (hsum2(d2) + hsum2(d3));
        float s = partial + __shfl_xor_sync(0xFFFFFFFFu, partial, 1);
        float w;
        if (s > m) {
            float scale = __expf(m - s);     // exp(-inf)=0 on first hit
            lsum *= scale;
            ull sc2 = dup2(scale);
            #pragma unroll
            for (int i = 0; i < 16; ++i) mul2(acc[i], acc[i], sc2);
            m = s;
            w = 1.0f;
        } else {
            w = __expf(s - m);
        }
        lsum += w;
        ull w2 = dup2(w);
        const ull* vv = (const ull*)(vvp + (k << 6));
        #pragma unroll
        for (int j = 0; j < 16; ++j) fma2(acc[j], w2, vv[j]);
    }

    float inv = 1.0f / lsum;
    float4* op = (float4*)(out + ((size_t)bh * LLn + qi) * DKk + hoff);
    #pragma unroll
    for (int j = 0; j < 8; ++j) {
        float4 a;
        unpack2(acc[2*j],   a.x, a.y);
        unpack2(acc[2*j+1], a.z, a.w);
        a.x *= inv; a.y *= inv; a.z *= inv; a.w *= inv;
        op[j] = a;
    }
}

// ---------------- 7. final loss composition ----------------
__global__ void loss_kernel(float* out_loss) {
    __shared__ float red[256];
    int tid = threadIdx.x;
    float s = 0.0f;
    for (int i = tid; i < MLP_BLOCKS; i += 256) s += g_lp[i];
    float c = 0.0f;
    for (int i = tid; i < 800; i += 256) c += g_ce[i];
    red[tid] = -s * (1.0f / (float)NROWS) + c * (1.0f / 800.0f);
    __syncthreads();
    for (int st = 128; st > 0; st >>= 1) {
        if (tid < st) red[tid] += red[tid + st];
        __syncthreads();
    }
    if (tid == 0) *out_loss = red[0];
}

// ---------------- host ----------------
extern "C" void kernel_launch(void* const* d_in, const int* in_sizes, int n_in,
                              void* d_out, int out_size) {
    const float* Q   = (const float*)d_in[0];
    const float* K   = (const float*)d_in[1];
    const float* V   = (const float*)d_in[2];
    const float* Wk1 = (const float*)d_in[3];
    const float* bk1 = (const float*)d_in[4];
    const float* Wk2 = (const float*)d_in[5];
    const float* bk2 = (const float*)d_in[6];
    const float* Wq1 = (const float*)d_in[7];
    const float* bq1 = (const float*)d_in[8];
    const float* Wq2 = (const float*)d_in[9];
    const float* bq2 = (const float*)d_in[10];
    const float* Wp  = (const float*)d_in[11];
    const float* bp  = (const float*)d_in[12];
    float* out = (float*)d_out;

    cudaFuncSetAttribute(mlp_kernel, cudaFuncAttributeMaxDynamicSharedMemorySize, 163840);
    cudaFuncSetAttribute(attn_kernel, cudaFuncAttributeMaxDynamicSharedMemorySize, 2 * LK * DKk * 4);

    pool_kernel<<<3648, 256>>>(K, V);
    mlp_kernel<<<MLP_BLOCKS, MLP_THREADS, 163840>>>(Wk1, bk1, Wk2, bk2, Wq1, bq1, Wq2, bq2);
    ce_kernel<<<BBa, 128>>>();
    centers_kernel<<<BBa * LK, 256>>>(Wp, bp);
    cc_kernel<<<912, 256>>>();

    if (out_size >= CTXN) {
        attn_kernel<<<512, 512, 2 * LK * DKk * 4>>>(Q, out);
    }
    if (out_size == CTXN + 1) {
        loss_kernel<<<1, 256>>>(out + CTXN);
    } else if (out_size == 1) {
        loss_kernel<<<1, 256>>>(out);
    }
}

// round 6
// speedup vs baseline: 1.2592x; 1.2592x over previous
#include <cuda_runtime.h>
#include <math.h>

// ---------------- problem constants ----------------
#define NCC 10
#define DM  512
#define HH  8
#define DKk 64
#define BBa 8
#define LLn 2048
#define LK  228
#define UF  100
#define NROWS (BBa*LK*UF)          // 182400
#define KPSZ  (512*LK)             // 116736 per batch
#define GSZ   (NCC*BBa*LK*DM)      // 9338880
#define CCSZ  (BBa*HH*LK*DKk)      // 933888
#define CTXN  (BBa*HH*LLn*DKk)     // 8388608
#define MLP_THREADS 384
#define MLP_BLOCKS (NROWS/MLP_THREADS)   // 475 exact

// ---------------- device scratch ----------------
__device__ float g_Kp[BBa*KPSZ];
__device__ float g_Vp[BBa*KPSZ];
__device__ float g_cq[NROWS*NCC];
__device__ float g_mu[NROWS];
__device__ float g_G[GSZ];
__device__ float g_CC[CCSZ];
__device__ float g_lp[MLP_BLOCKS];
__device__ float g_ce[800];

// ---------------- helpers ----------------
__device__ __forceinline__ float gelu_exact(float x) {
    return 0.5f * x * (1.0f + erff(x * 0.70710678118654752f));
}

typedef unsigned long long ull;
__device__ __forceinline__ void fma2(ull& d, ull a, ull b) {
    asm("fma.rn.f32x2 %0, %1, %2, %0;" : "+l"(d) : "l"(a), "l"(b));
}
__device__ __forceinline__ void mul2(ull& d, ull a, ull b) {
    asm("mul.rn.f32x2 %0, %1, %2;" : "=l"(d) : "l"(a), "l"(b));
}
__device__ __forceinline__ ull pack2(float lo, float hi) {
    ull v;
    asm("mov.b64 %0, {%1, %2};" : "=l"(v) : "r"(__float_as_uint(lo)), "r"(__float_as_uint(hi)));
    return v;
}
__device__ __forceinline__ ull dup2(float x) { return pack2(x, x); }
__device__ __forceinline__ void unpack2(ull v, float& lo, float& hi) {
    unsigned int a, b;
    asm("mov.b64 {%0, %1}, %2;" : "=r"(a), "=r"(b) : "l"(v));
    lo = __uint_as_float(a); hi = __uint_as_float(b);
}
__device__ __forceinline__ float hsum2(ull v) {
    float lo, hi; unpack2(v, lo, hi); return lo + hi;
}

// ---------------- 1. max pool ----------------
__global__ void pool_kernel(const float* __restrict__ K, const float* __restrict__ V) {
    int idx = blockIdx.x * 256 + threadIdx.x;           // < 933888
    int b = idx / KPSZ;
    int rem = idx - b * KPSZ;
    int c = rem / LK;
    int t2 = rem - c * LK;
    int t0 = t2 * 9 - 4;
    int lo = t0 < 0 ? 0 : t0;
    int hi = t0 + 9 > 2048 ? 2048 : t0 + 9;
    const float* kp = K + ((size_t)b * 512 + c) * 2048;
    const float* vp = V + ((size_t)b * 512 + c) * 2048;
    float mk = -INFINITY, mv = -INFINITY;
    for (int t = lo; t < hi; ++t) { mk = fmaxf(mk, kp[t]); mv = fmaxf(mv, vp[t]); }
    g_Kp[idx] = mk;
    g_Vp[idx] = mv;
}

// ---------------- 2. sparse-gather double MLP (packed f32x2) ----------------
__global__ __launch_bounds__(MLP_THREADS) void mlp_kernel(
    const float* __restrict__ Wk1, const float* __restrict__ bk1,
    const float* __restrict__ Wk2, const float* __restrict__ bk2,
    const float* __restrict__ Wq1, const float* __restrict__ bq1,
    const float* __restrict__ Wq2, const float* __restrict__ bq2)
{
    extern __shared__ float sw[];
    float* sWk1 = sw;               // 512*40
    float* sWq1 = sw + 20480;       // 512*40
    __shared__ __align__(16) float sWk2[400], sWq2[400];
    __shared__ __align__(16) float sbk1[40], sbq1[40], sbk2[16], sbq2[16];
    __shared__ float warpsum[12];
    for (int i = threadIdx.x; i < 20480; i += MLP_THREADS) { sWk1[i] = Wk1[i]; sWq1[i] = Wq1[i]; }
    for (int i = threadIdx.x; i < 400; i += MLP_THREADS) { sWk2[i] = Wk2[i]; sWq2[i] = Wq2[i]; }
    if (threadIdx.x < 40) { sbk1[threadIdx.x] = bk1[threadIdx.x]; sbq1[threadIdx.x] = bq1[threadIdx.x]; }
    if (threadIdx.x < 10) { sbk2[threadIdx.x] = bk2[threadIdx.x]; sbq2[threadIdx.x] = bq2[threadIdx.x]; }
    __syncthreads();

    int r = blockIdx.x * MLP_THREADS + threadIdx.x;   // always < NROWS (exact grid)
    float lp;
    {
        int b  = r / (LK * UF);
        int l2 = (r / UF) % LK;
        int u2 = r % UF;

        ull ak2[20], aq2[20];
        {
            const ull* pk = (const ull*)sbk1;
            const ull* pq = (const ull*)sbq1;
            #pragma unroll
            for (int j = 0; j < 20; ++j) { ak2[j] = pk[j]; aq2[j] = pq[j]; }
        }

        int m12 = (12 * u2) % 100;
        int base = u2 * 512;
        for (int u = 100 - b; u < 100; ++u) {      // empty when b == 0
            int bp_ = u + b - 99;                  // source batch 1..b
            int c0 = u - m12; if (c0 < 0) c0 += 100;
            const float* kpr = g_Kp + bp_ * KPSZ + l2 * 512;
            for (int c2 = c0; c2 < 512; c2 += 100) {
                int q = (base + c2 - u) / 100;     // exact division
                ull v2 = dup2(__ldg(kpr + q));
                const ull* w1 = (const ull*)(sWk1 + c2 * 40);
                const ull* w2 = (const ull*)(sWq1 + c2 * 40);
                #pragma unroll
                for (int jj = 0; jj < 20; ++jj) {
                    fma2(ak2[jj], v2, w1[jj]);
                    fma2(aq2[jj], v2, w2[jj]);
                }
            }
        }
        float hk[40], hq[40];
        #pragma unroll
        for (int j = 0; j < 20; ++j) {
            unpack2(ak2[j], hk[2*j], hk[2*j+1]);
            unpack2(aq2[j], hq[2*j], hq[2*j+1]);
        }
        #pragma unroll
        for (int j = 0; j < 40; ++j) { hk[j] = gelu_exact(hk[j]); hq[j] = gelu_exact(hq[j]); }

        ull ok2[5], oq2[5];
        {
            const ull* pk = (const ull*)sbk2;
            const ull* pq = (const ull*)sbq2;
            #pragma unroll
            for (int p = 0; p < 5; ++p) { ok2[p] = pk[p]; oq2[p] = pq[p]; }
        }
        #pragma unroll
        for (int j = 0; j < 40; ++j) {
            ull hk2 = dup2(hk[j]);
            ull hq2 = dup2(hq[j]);
            const ull* w2k = (const ull*)(sWk2 + j * 10);
            const ull* w2q = (const ull*)(sWq2 + j * 10);
            #pragma unroll
            for (int p = 0; p < 5; ++p) {
                fma2(ok2[p], hk2, w2k[p]);
                fma2(oq2[p], hq2, w2q[p]);
            }
        }
        float ok[10], oq[10];
        #pragma unroll
        for (int p = 0; p < 5; ++p) {
            unpack2(ok2[p], ok[2*p], ok[2*p+1]);
            unpack2(oq2[p], oq[2*p], oq[2*p+1]);
        }
        float mk = ok[0], mq = oq[0];
        #pragma unroll
        for (int i = 1; i < 10; ++i) { mk = fmaxf(mk, ok[i]); mq = fmaxf(mq, oq[i]); }
        float sk = 0.0f, sq = 0.0f;
        float ckv[10], cqv[10];
        #pragma unroll
        for (int i = 0; i < 10; ++i) {
            ckv[i] = __expf(ok[i] - mk); sk += ckv[i];
            cqv[i] = __expf(oq[i] - mq); sq += cqv[i];
        }
        float isk = 1.0f / sk, isq = 1.0f / sq;
        float* dst = g_cq + (size_t)r * NCC;
        float sumq = 0.0f, sumk = 0.0f;
        #pragma unroll
        for (int i = 0; i < 10; ++i) {
            ckv[i] *= isk; cqv[i] *= isq;
            dst[i] = cqv[i];
            sumq += cqv[i]; sumk += ckv[i];
        }
        float mu = sumq * 0.1f;
        float x  = sumk * 0.1f;
        float ssd = 0.0f;
        #pragma unroll
        for (int i = 0; i < 10; ++i) { float d = cqv[i] - mu; ssd = fmaf(d, d, ssd); }
        float stdv = sqrtf(ssd * (1.0f / 9.0f));
        float sigma = log1pf(__expf(stdv));      // softplus
        float z = (x - mu) / sigma;
        lp = -0.5f * z * z - logf(sigma) - 0.9189385332046727f;
        g_mu[r] = mu;
    }
    // deterministic reduction
    #pragma unroll
    for (int o = 16; o; o >>= 1) lp += __shfl_xor_sync(0xFFFFFFFFu, lp, o);
    int wid = threadIdx.x >> 5;
    if ((threadIdx.x & 31) == 0) warpsum[wid] = lp;
    __syncthreads();
    if (threadIdx.x == 0) {
        float s = 0.0f;
        #pragma unroll
        for (int i = 0; i < 12; ++i) s += warpsum[i];
        g_lp[blockIdx.x] = s;
    }
}

// ---------------- 3. CE (branchless online LSE, coalesced lanes) ----------------
__global__ void ce_kernel() {
    int b = blockIdx.x;
    int u = threadIdx.x;
    if (u >= UF) return;
    const float* p = g_mu + (size_t)b * LK * UF + u;
    float m = -INFINITY, se = 0.0f, s1 = 0.0f, s2 = 0.0f;
    #pragma unroll 4
    for (int l = 0; l < LK; ++l) {
        float v = p[l * UF];
        float mn = fmaxf(m, v);
        se = fmaf(se, __expf(m - mn), __expf(v - mn));
        m = mn;
        s1 += v;
        s2 = fmaf(v, v, s2);
    }
    float lse = m + logf(se);
    g_ce[b * UF + u] = lse * s1 - s2;   // = -sum_l mu*(mu - lse)
}

// ---------------- 4. centers + proj_back (packed f32x2) ----------------
__global__ __launch_bounds__(256) void centers_kernel(const float* __restrict__ Wp, const float* __restrict__ bp) {
    int bl = blockIdx.x;            // 0..1823  (= bb*228 + l)
    int bb = bl / LK, l = bl % LK;
    __shared__ __align__(16) float scq[UF * NCC];   // 1000
    __shared__ int   sassign[UF];
    __shared__ float scen[NCC * NCC]; // 100
    __shared__ __align__(16) float sWp[NCC * DM];   // 5120
    __shared__ __align__(16) float sbp[DM];
    {
        const float4* src = (const float4*)(g_cq + (size_t)bl * UF * NCC);
        for (int i = threadIdx.x; i < UF * NCC / 4; i += 256) ((float4*)scq)[i] = src[i];
        const float4* wsrc = (const float4*)Wp;
        for (int i = threadIdx.x; i < NCC * DM / 4; i += 256) ((float4*)sWp)[i] = wsrc[i];
        const float4* bsrc = (const float4*)bp;
        for (int i = threadIdx.x; i < DM / 4; i += 256) ((float4*)sbp)[i] = bsrc[i];
    }
    __syncthreads();
    if (threadIdx.x < UF) {
        const float* row = scq + threadIdx.x * NCC;
        int am = 0; float mv = row[0];
        #pragma unroll
        for (int c = 1; c < NCC; ++c) if (row[c] > mv) { mv = row[c]; am = c; }
        sassign[threadIdx.x] = am;
    }
    __syncthreads();
    if (threadIdx.x < 100) {
        int i = threadIdx.x / 10, c = threadIdx.x % 10;
        float s = 0.0f;
        for (int u = 0; u < UF; ++u)
            if (sassign[u] != i) s += scq[u * NCC + c];
        scen[i * 10 + c] = s * 0.01f;
    }
    __syncthreads();
    // projection: 1280 float4 outputs, 5 per thread, packed fma
    for (int i4 = threadIdx.x; i4 < NCC * (DM/4); i4 += 256) {
        int i = i4 >> 7;            // cluster index 0..9
        int m4 = i4 & 127;          // float4 index within 512
        ull d0 = ((const ull*)sbp)[2*m4];
        ull d1 = ((const ull*)sbp)[2*m4+1];
        const float* ce = scen + i * 10;
        #pragma unroll
        for (int c = 0; c < NCC; ++c) {
            const ull* wv = (const ull*)(sWp + c * DM + 4*m4);
            ull cv = dup2(ce[c]);
            fma2(d0, cv, wv[0]);
            fma2(d1, cv, wv[1]);
        }
        float4 a;
        unpack2(d0, a.x, a.y);
        unpack2(d1, a.z, a.w);
        a.x = gelu_exact(a.x); a.y = gelu_exact(a.y);
        a.z = gelu_exact(a.z); a.w = gelu_exact(a.w);
        ((float4*)(g_G + (size_t)i * (BBa * LK * DM) + bb * (LK * DM) + l * DM))[m4] = a;
    }
}

// ---------------- 5. CC: reshape-sum over the 10 'c' slices (float4) ----------------
__global__ void cc_kernel() {
    int o4 = blockIdx.x * 256 + threadIdx.x;       // < 233472
    if (o4 >= CCSZ / 4) return;
    int o = o4 * 4;
    int b2 = o / (HH * LK * DKk);
    int h2 = (o / (LK * DKk)) % HH;
    int rest = o % (LK * DKk);
    int basei4 = (b2 * 1167360 + h2 * 145920 + rest) >> 2;
    const float4* G4 = (const float4*)g_G;
    float4 s = G4[basei4];
    #pragma unroll
    for (int i2 = 1; i2 < NCC; ++i2) {
        float4 t = G4[basei4 + i2 * 3648];
        s.x += t.x; s.y += t.y; s.z += t.z; s.w += t.w;
    }
    ((float4*)g_CC)[o4] = s;
}

// ---------------- 6. attention: 2-k unrolled dual dot-chains, online softmax ----------------
__global__ __launch_bounds__(256, 1) void attn_kernel(const float* __restrict__ Q, float* __restrict__ out) {
    extern __shared__ float sm[];
    float* sCC = sm;                  // 228*64
    float* sV  = sm + LK * DKk;       // 228*64
    int bh = blockIdx.x >> 3;         // 0..63
    int qt = blockIdx.x & 7;
    int b = bh >> 3, h = bh & 7;
    {
        const float4* srcC = (const float4*)(g_CC + (size_t)bh * (LK * DKk));
        const float4* srcV = (const float4*)(g_Vp + (size_t)b * KPSZ + h * (LK * DKk));
        float4* dC = (float4*)sCC;
        float4* dV = (float4*)sV;
        for (int i = threadIdx.x; i < LK * DKk / 4; i += 256) { dC[i] = srcC[i]; dV[i] = srcV[i]; }
    }
    __syncthreads();

    int qi = qt * 256 + threadIdx.x;
    ulonglong2 qv[16];
    {
        const float4* qr = (const float4*)(Q + ((size_t)bh * LLn + qi) * DKk);
        #pragma unroll
        for (int j = 0; j < 16; ++j) {
            float4 t = qr[j];
            qv[j].x = pack2(t.x * 0.125f, t.y * 0.125f);
            qv[j].y = pack2(t.z * 0.125f, t.w * 0.125f);
        }
    }

    float m = -INFINITY, lsum = 0.0f;
    ull acc[32];
    #pragma unroll
    for (int i = 0; i < 32; ++i) acc[i] = 0ull;

    for (int k = 0; k < LK; k += 2) {      // LK=228 even
        const ulonglong2* cc0 = (const ulonglong2*)(sCC + (k << 6));
        const ulonglong2* cc1 = (const ulonglong2*)(sCC + ((k + 1) << 6));
        // two independent dot-product chains (ILP across the k-pair)
        ull a0 = 0ull, a1 = 0ull, a2 = 0ull, a3 = 0ull;
        ull b0 = 0ull, b1 = 0ull, b2 = 0ull, b3 = 0ull;
        #pragma unroll
        for (int j = 0; j < 16; j += 2) {
            ulonglong2 c0 = cc0[j];
            ulonglong2 c1 = cc0[j + 1];
            ulonglong2 e0 = cc1[j];
            ulonglong2 e1 = cc1[j + 1];
            fma2(a0, qv[j].x, c0.x);
            fma2(b0, qv[j].x, e0.x);
            fma2(a1, qv[j].y, c0.y);
            fma2(b1, qv[j].y, e0.y);
            fma2(a2, qv[j + 1].x, c1.x);
            fma2(b2, qv[j + 1].x, e1.x);
            fma2(a3, qv[j + 1].y, c1.y);
            fma2(b3, qv[j + 1].y, e1.y);
        }
        float s0 = (hsum2(a0) + hsum2(a1)) + (hsum2(a2) + hsum2(a3));
        float s1 = (hsum2(b0) + hsum2(b1)) + (hsum2(b2) + hsum2(b3));

        float mn = fmaxf(m, fmaxf(s0, s1));
        float w0 = __expf(s0 - mn);
        float w1 = __expf(s1 - mn);
        if (mn > m) {                          // rare after warmup
            float scale = __expf(m - mn);      // exp(-inf)=0 on first hit
            lsum *= scale;
            ull sc2 = dup2(scale);
            #pragma unroll
            for (int i = 0; i < 32; ++i) mul2(acc[i], acc[i], sc2);
            m = mn;
        }
        lsum += w0 + w1;
        ull w02 = dup2(w0);
        ull w12 = dup2(w1);
        const ulonglong2* v0 = (const ulonglong2*)(sV + (k << 6));
        const ulonglong2* v1 = (const ulonglong2*)(sV + ((k + 1) << 6));
        #pragma unroll
        for (int j = 0; j < 16; ++j) {
            ulonglong2 va = v0[j];
            ulonglong2 vb = v1[j];
            fma2(acc[2 * j],     w02, va.x);
            fma2(acc[2 * j + 1], w02, va.y);
            fma2(acc[2 * j],     w12, vb.x);
            fma2(acc[2 * j + 1], w12, vb.y);
        }
    }

    float inv = 1.0f / lsum;
    float* op = out + ((size_t)bh * LLn + qi) * DKk;
    #pragma unroll
    for (int i = 0; i < 32; ++i) {
        float lo, hi; unpack2(acc[i], lo, hi);
        op[2 * i]     = lo * inv;
        op[2 * i + 1] = hi * inv;
    }
}

// ---------------- 7. final loss composition ----------------
__global__ void loss_kernel(float* out_loss) {
    __shared__ float red[256];
    int tid = threadIdx.x;
    float s = 0.0f;
    for (int i = tid; i < MLP_BLOCKS; i += 256) s += g_lp[i];
    float c = 0.0f;
    for (int i = tid; i < 800; i += 256) c += g_ce[i];
    red[tid] = -s * (1.0f / (float)NROWS) + c * (1.0f / 800.0f);
    __syncthreads();
    for (int st = 128; st > 0; st >>= 1) {
        if (tid < st) red[tid] += red[tid + st];
        __syncthreads();
    }
    if (tid == 0) *out_loss = red[0];
}

// ---------------- host ----------------
extern "C" void kernel_launch(void* const* d_in, const int* in_sizes, int n_in,
                              void* d_out, int out_size) {
    const float* Q   = (const float*)d_in[0];
    const float* K   = (const float*)d_in[1];
    const float* V   = (const float*)d_in[2];
    const float* Wk1 = (const float*)d_in[3];
    const float* bk1 = (const float*)d_in[4];
    const float* Wk2 = (const float*)d_in[5];
    const float* bk2 = (const float*)d_in[6];
    const float* Wq1 = (const float*)d_in[7];
    const float* bq1 = (const float*)d_in[8];
    const float* Wq2 = (const float*)d_in[9];
    const float* bq2 = (const float*)d_in[10];
    const float* Wp  = (const float*)d_in[11];
    const float* bp  = (const float*)d_in[12];
    float* out = (float*)d_out;

    cudaFuncSetAttribute(mlp_kernel, cudaFuncAttributeMaxDynamicSharedMemorySize, 163840);
    cudaFuncSetAttribute(attn_kernel, cudaFuncAttributeMaxDynamicSharedMemorySize, 2 * LK * DKk * 4);

    pool_kernel<<<3648, 256>>>(K, V);
    mlp_kernel<<<MLP_BLOCKS, MLP_THREADS, 163840>>>(Wk1, bk1, Wk2, bk2, Wq1, bq1, Wq2, bq2);
    ce_kernel<<<BBa, 128>>>();
    centers_kernel<<<BBa * LK, 256>>>(Wp, bp);
    cc_kernel<<<912, 256>>>();

    if (out_size >= CTXN) {
        attn_kernel<<<512, 256, 2 * LK * DKk * 4>>>(Q, out);
    }
    if (out_size == CTXN + 1) {
        loss_kernel<<<1, 256>>>(out + CTXN);
    } else if (out_size == 1) {
        loss_kernel<<<1, 256>>>(out);
    }
}